// round 13
// baseline (speedup 1.0000x reference)
#include <cuda_runtime.h>
#include <cuda_bf16.h>
#include <cstdint>

#define N_NODES  150000
#define N_PAD    150016          // 1172 * 128
#define N_EDGES  2400000
#define NEG_SLOPE 0.01f
#define TILE_NODES 128
#define N_TILES  (N_PAD / TILE_NODES)   // 1172
#define UPD_GRID 148                    // persistent: 1 block per SM

// update kernel dynamic smem layout (bytes)
#define OFF_E0 0
#define OFF_S0 32768
#define OFF_E1 65536
#define OFF_S1 98304
#define OFF_A  131072
#define OFF_P  163840
#define OFF_W1 196608
#define OFF_W2 212992
#define UPD_SMEM_BYTES 229376            // <= 232448 cap

__device__ __align__(1024) float    g_ego [N_PAD * 64];
__device__ __align__(1024) float    g_side[N_PAD * 64];
__device__ __align__(1024) uint32_t g_ego_bf[N_PAD * 32];   // bf16x2 mirror

__device__ __forceinline__ uint32_t smem_u32(const void* p) {
    uint32_t a;
    asm("{ .reg .u64 t; cvta.to.shared.u64 t, %1; cvt.u32.u64 %0, t; }"
        : "=r"(a) : "l"(p));
    return a;
}
__device__ __forceinline__ void cp16(uint32_t dst, const float* src) {
    asm volatile("cp.async.cg.shared.global [%0], [%1], 16;"
                 :: "r"(dst), "l"(src) : "memory");
}
__device__ __forceinline__ uint32_t packbf(float a, float b) {
    __nv_bfloat162 h = __floats2bfloat162_rn(a, b);   // a->low, b->high
    return *(uint32_t*)&h;
}

// ---------------------------------------------------------------------------
__global__ void dummy_kernel() {          // keeps ncu -s 5 on update #2
    if (blockIdx.x == 0x40000000) g_side[0] = 0.f;
}

__global__ void init_kernel(const float* __restrict__ ego_in,
                            float* __restrict__ out) {
    int t = blockIdx.x * 256 + threadIdx.x;          // float4 idx < N_PAD*16
    bool real = (t < N_NODES * 16);
    float4 v = real ? ((const float4*)ego_in)[t]
                    : make_float4(0.f, 0.f, 0.f, 0.f);
    ((float4*)g_ego)[t]  = v;
    ((float4*)g_side)[t] = make_float4(0.f, 0.f, 0.f, 0.f);
    g_ego_bf[t * 2]     = packbf(v.x, v.y);
    g_ego_bf[t * 2 + 1] = packbf(v.z, v.w);
    if (real) {
        int i = t >> 4, c = t & 15;
        ((float4*)out)[i * 64 + c] = v;
    }
}

// ---------------------------------------------------------------------------
// spmm: side[row] += val * ego_bf16[col]. 4 edges/thread, 8 threads/edge
// (16B bf16 chunk each = 8 elems). Gather reads halved vs fp32 (128B/edge);
// REDs stay fp32 v4 (accumulation precision & write path unchanged).
// ---------------------------------------------------------------------------
__device__ __forceinline__ void red8(float v, uint4 x, float* dst) {
    float f0 = __uint_as_float(x.x << 16);
    float f1 = __uint_as_float(x.x & 0xffff0000u);
    float f2 = __uint_as_float(x.y << 16);
    float f3 = __uint_as_float(x.y & 0xffff0000u);
    float f4 = __uint_as_float(x.z << 16);
    float f5 = __uint_as_float(x.z & 0xffff0000u);
    float f6 = __uint_as_float(x.w << 16);
    float f7 = __uint_as_float(x.w & 0xffff0000u);
    asm volatile("red.global.add.v4.f32 [%0], {%1,%2,%3,%4};"
                 :: "l"(dst), "f"(v*f0), "f"(v*f1), "f"(v*f2), "f"(v*f3) : "memory");
    asm volatile("red.global.add.v4.f32 [%0], {%1,%2,%3,%4};"
                 :: "l"(dst + 4), "f"(v*f4), "f"(v*f5), "f"(v*f6), "f"(v*f7) : "memory");
}

__global__ void __launch_bounds__(256) spmm_kernel(
        const int*   __restrict__ rows,
        const int*   __restrict__ cols,
        const float* __restrict__ vals) {
    int t = blockIdx.x * 256 + threadIdx.x;   // < (E/4)*8
    int g = t >> 3;        // edge group of 4
    int c = t & 7;         // 16B chunk (8 bf16) within the 128B row
    int4   r4 = __ldg((const int4*)  rows + g);
    int4   c4 = __ldg((const int4*)  cols + g);
    float4 v4 = __ldg((const float4*)vals + g);
    const uint4* egob = (const uint4*)g_ego_bf;
    uint4 x0 = __ldg(egob + (c4.x * 8 + c));
    uint4 x1 = __ldg(egob + (c4.y * 8 + c));
    uint4 x2 = __ldg(egob + (c4.z * 8 + c));
    uint4 x3 = __ldg(egob + (c4.w * 8 + c));
    red8(v4.x, x0, g_side + r4.x * 64 + c * 8);
    red8(v4.y, x1, g_side + r4.y * 64 + c * 8);
    red8(v4.z, x2, g_side + r4.z * 64 + c * 8);
    red8(v4.w, x3, g_side + r4.w * 64 + c * 8);
}

// ---------------------------------------------------------------------------
// Issue cp.async loads for one tile's raw ego/side (128 nodes x 64 f32 each).
// Chunk swizzle (c4 ^ (node&15)) spreads banks for the transform reads.
// ---------------------------------------------------------------------------
__device__ __forceinline__ void issue_tile(char* sm, int buf, int tile, int tid) {
    uint32_t dE = smem_u32(sm + (buf ? OFF_E1 : OFF_E0));
    uint32_t dS = smem_u32(sm + (buf ? OFF_S1 : OFF_S0));
    const float* srcE = g_ego  + tile * (TILE_NODES * 64);
    const float* srcS = g_side + tile * (TILE_NODES * 64);
    #pragma unroll
    for (int it = 0; it < 8; it++) {
        int id   = it * 256 + tid;       // 0..2047
        int node = id >> 4;
        int c4   = id & 15;
        uint32_t dof = node * 256 + ((c4 ^ (node & 15)) << 4);
        int sof = node * 64 + c4 * 4;
        cp16(dE + dof, srcE + sof);
        cp16(dS + dof, srcS + sof);
    }
}

// ---------------------------------------------------------------------------
// Persistent dual-GEMM update (round-12 WIN structure, unchanged math).
// Adds: epilogue writes bf16 mirror of next-layer ego for spmm.
// ---------------------------------------------------------------------------
__global__ void __launch_bounds__(256) update_kernel(
        const float* __restrict__ W1, const float* __restrict__ b1,
        const float* __restrict__ W2, const float* __restrict__ b2,
        float* __restrict__ out, int col4, int last) {
    extern __shared__ char sm[];
    int tid = threadIdx.x;
    int tx  = tid & 7;                // dim octet: dims tx*8 .. +7
    int ny  = tid >> 3;               // node quad: nodes ny*4 .. +3

    float b1v[8], b2v[8];
    #pragma unroll
    for (int d = 0; d < 8; d++) {
        b1v[d] = __ldg(b1 + tx * 8 + d);
        b2v[d] = __ldg(b2 + tx * 8 + d);
    }

    // stage W1/W2 k-major once per block
    float* sW1 = (float*)(sm + OFF_W1);
    float* sW2 = (float*)(sm + OFF_W2);
    for (int idx = tid; idx < 1024; idx += 256) {
        int kc = idx >> 6, j = idx & 63;
        float4 w1 = __ldg((const float4*)W1 + j * 16 + kc);
        float4 w2 = __ldg((const float4*)W2 + j * 16 + kc);
        int k0 = 4 * kc;
        sW1[(k0+0)*64 + j] = w1.x; sW1[(k0+1)*64 + j] = w1.y;
        sW1[(k0+2)*64 + j] = w1.z; sW1[(k0+3)*64 + j] = w1.w;
        sW2[(k0+0)*64 + j] = w2.x; sW2[(k0+1)*64 + j] = w2.y;
        sW2[(k0+2)*64 + j] = w2.z; sW2[(k0+3)*64 + j] = w2.w;
    }

    issue_tile(sm, 0, blockIdx.x, tid);
    asm volatile("cp.async.commit_group;" ::: "memory");

    int lt = 0;
    for (int t = blockIdx.x; t < N_TILES; t += UPD_GRID, lt++) {
        int buf = lt & 1;
        __syncthreads();                       // buffer buf^1 free to refill
        int tn = t + UPD_GRID;
        if (tn < N_TILES) {
            issue_tile(sm, buf ^ 1, tn, tid);
            asm volatile("cp.async.commit_group;" ::: "memory");
            asm volatile("cp.async.wait_group 1;" ::: "memory");
        } else {
            asm volatile("cp.async.wait_group 0;" ::: "memory");
        }
        __syncthreads();                       // tile t raw data visible

        // transform raw -> A (k-major), P (k-major)
        const char* bE = sm + (buf ? OFF_E1 : OFF_E0);
        const char* bS = sm + (buf ? OFF_S1 : OFF_S0);
        float* A = (float*)(sm + OFF_A);
        float* P = (float*)(sm + OFF_P);
        #pragma unroll
        for (int it = 0; it < 8; it++) {
            int idx  = it * 256 + tid;        // 0..2047
            int c4   = idx >> 7;              // k chunk 0..15
            int node = idx & 127;
            uint32_t ro = node * 256 + ((c4 ^ (node & 15)) << 4);
            float4 e = *(const float4*)(bE + ro);
            float4 s = *(const float4*)(bS + ro);
            int k0 = 4 * c4;
            A[(k0+0)*128 + node] = e.x + s.x;  P[(k0+0)*128 + node] = e.x * s.x;
            A[(k0+1)*128 + node] = e.y + s.y;  P[(k0+1)*128 + node] = e.y * s.y;
            A[(k0+2)*128 + node] = e.z + s.z;  P[(k0+2)*128 + node] = e.z * s.z;
            A[(k0+3)*128 + node] = e.w + s.w;  P[(k0+3)*128 + node] = e.w * s.w;
        }
        __syncthreads();

        // mainloop: 6 LDS.128 + 64 FMA per k
        float acc1[32], acc2[32];
        #pragma unroll
        for (int i = 0; i < 32; i++) { acc1[i] = 0.f; acc2[i] = 0.f; }

        const float4* A4  = (const float4*)(sm + OFF_A);
        const float4* P4  = (const float4*)(sm + OFF_P);
        const float4* W14 = (const float4*)(sm + OFF_W1);
        const float4* W24 = (const float4*)(sm + OFF_W2);

        #pragma unroll 4
        for (int k = 0; k < 64; k++) {
            float4 a   = A4 [k * 32 + ny];
            float4 p   = P4 [k * 32 + ny];
            float4 w1a = W14[k * 16 + tx * 2];
            float4 w1b = W14[k * 16 + tx * 2 + 1];
            float4 w2a = W24[k * 16 + tx * 2];
            float4 w2b = W24[k * 16 + tx * 2 + 1];
            float av[4] = {a.x, a.y, a.z, a.w};
            float pv[4] = {p.x, p.y, p.z, p.w};
            float w1[8] = {w1a.x, w1a.y, w1a.z, w1a.w, w1b.x, w1b.y, w1b.z, w1b.w};
            float w2[8] = {w2a.x, w2a.y, w2a.z, w2a.w, w2b.x, w2b.y, w2b.z, w2b.w};
            #pragma unroll
            for (int n = 0; n < 4; n++)
                #pragma unroll
                for (int d = 0; d < 8; d++) {
                    acc1[n * 8 + d] = fmaf(av[n], w1[d], acc1[n * 8 + d]);
                    acc2[n * 8 + d] = fmaf(pv[n], w2[d], acc2[n * 8 + d]);
                }
        }

        // epilogue
        #pragma unroll
        for (int n = 0; n < 4; n++) {
            float v[8], ss = 0.f;
            #pragma unroll
            for (int d = 0; d < 8; d++) {
                float y1 = acc1[n * 8 + d] + b1v[d];
                float y2 = acc2[n * 8 + d] + b2v[d];
                y1 = (y1 >= 0.f) ? y1 : NEG_SLOPE * y1;
                y2 = (y2 >= 0.f) ? y2 : NEG_SLOPE * y2;
                v[d] = y1 + y2;
                ss += v[d] * v[d];
            }
            ss += __shfl_xor_sync(0xffffffffu, ss, 1);
            ss += __shfl_xor_sync(0xffffffffu, ss, 2);
            ss += __shfl_xor_sync(0xffffffffu, ss, 4);
            float inv = 1.0f / fmaxf(sqrtf(ss), 1e-12f);
            int i = t * TILE_NODES + ny * 4 + n;
            float4 lo = make_float4(v[0], v[1], v[2], v[3]);
            float4 hi = make_float4(v[4], v[5], v[6], v[7]);
            if (!last) {
                ((float4*)g_ego)[i * 16 + tx * 2]     = lo;
                ((float4*)g_ego)[i * 16 + tx * 2 + 1] = hi;
                uint4 bf = make_uint4(packbf(v[0], v[1]), packbf(v[2], v[3]),
                                      packbf(v[4], v[5]), packbf(v[6], v[7]));
                ((uint4*)g_ego_bf)[i * 8 + tx] = bf;
            }
            if (i < N_NODES) {
                ((float4*)out)[i * 64 + col4 + tx * 2] =
                    make_float4(lo.x*inv, lo.y*inv, lo.z*inv, lo.w*inv);
                ((float4*)out)[i * 64 + col4 + tx * 2 + 1] =
                    make_float4(hi.x*inv, hi.y*inv, hi.z*inv, hi.w*inv);
            }
        }

        // zero g_side tile for next layer's spmm
        if (!last) {
            float4 z = make_float4(0.f, 0.f, 0.f, 0.f);
            #pragma unroll
            for (int it = 0; it < 8; it++)
                ((float4*)g_side)[t * 2048 + it * 256 + tid] = z;
        }
    }
}

// ---------------------------------------------------------------------------
// Inputs: edge_rows(i32), edge_cols(i32), edge_vals(f32), ego(f32 N*64),
// W1(3*64*64), b1(3*64), W2(3*64*64), b2(3*64).
// Output: float32 [150000, 256] rows = [ego | norm1 | norm2 | norm3].
// ---------------------------------------------------------------------------
extern "C" void kernel_launch(void* const* d_in, const int* in_sizes, int n_in,
                              void* d_out, int out_size) {
    const int*   rows = (const int*)  d_in[0];
    const int*   cols = (const int*)  d_in[1];
    const float* vals = (const float*)d_in[2];
    const float* ego  = (const float*)d_in[3];
    const float* W1   = (const float*)d_in[4];
    const float* b1   = (const float*)d_in[5];
    const float* W2   = (const float*)d_in[6];
    const float* b2   = (const float*)d_in[7];
    float* out = (float*)d_out;

    cudaFuncSetAttribute(update_kernel,
                         cudaFuncAttributeMaxDynamicSharedMemorySize,
                         UPD_SMEM_BYTES);

    dummy_kernel<<<1, 32>>>();                                    // launch 0
    init_kernel<<<(N_PAD * 16) / 256, 256>>>(ego, out);           // launch 1
    for (int k = 0; k < 3; k++) {
        spmm_kernel<<<(N_EDGES / 4 * 8) / 256, 256>>>(rows, cols, vals);
        update_kernel<<<UPD_GRID, 256, UPD_SMEM_BYTES>>>(
            W1 + k * 4096, b1 + k * 64,
            W2 + k * 4096, b2 + k * 64,
            out, (k + 1) * 16, k == 2);
    }
}

// round 15
// speedup vs baseline: 1.2586x; 1.2586x over previous
#include <cuda_runtime.h>
#include <cuda_bf16.h>
#include <cstdint>

#define N_NODES  150000
#define N_PAD    150016          // 1172 * 128
#define N_EDGES  2400000
#define NEG_SLOPE 0.01f
#define TILE_NODES 128
#define N_TILES  (N_PAD / TILE_NODES)   // 1172
#define UPD_GRID 148                    // persistent: 1 block per SM

// update kernel dynamic smem layout (bytes)
#define OFF_E0 0
#define OFF_S0 32768
#define OFF_E1 65536
#define OFF_S1 98304
#define OFF_A  131072
#define OFF_P  163840
#define OFF_W1 196608
#define OFF_W2 212992
#define UPD_SMEM_BYTES 229376            // <= 232448 cap

__device__ __align__(1024) float    g_ego [N_PAD * 64];
__device__ __align__(1024) float    g_side[N_PAD * 64];
__device__ __align__(1024) uint32_t g_ego_bf[N_PAD * 32];   // bf16x2 mirror

__device__ __forceinline__ uint32_t smem_u32(const void* p) {
    uint32_t a;
    asm("{ .reg .u64 t; cvta.to.shared.u64 t, %1; cvt.u32.u64 %0, t; }"
        : "=r"(a) : "l"(p));
    return a;
}
__device__ __forceinline__ void cp16(uint32_t dst, const float* src) {
    asm volatile("cp.async.cg.shared.global [%0], [%1], 16;"
                 :: "r"(dst), "l"(src) : "memory");
}
__device__ __forceinline__ uint32_t packbf(float a, float b) {
    __nv_bfloat162 h = __floats2bfloat162_rn(a, b);   // a->low, b->high
    return *(uint32_t*)&h;
}

// ---------------------------------------------------------------------------
__global__ void dummy_kernel() {          // keeps ncu -s 5 on update #2
    if (blockIdx.x == 0x40000000) g_side[0] = 0.f;
}

__global__ void init_kernel(const float* __restrict__ ego_in,
                            float* __restrict__ out) {
    int t = blockIdx.x * 256 + threadIdx.x;          // float4 idx < N_PAD*16
    bool real = (t < N_NODES * 16);
    float4 v = real ? ((const float4*)ego_in)[t]
                    : make_float4(0.f, 0.f, 0.f, 0.f);
    ((float4*)g_ego)[t]  = v;
    ((float4*)g_side)[t] = make_float4(0.f, 0.f, 0.f, 0.f);
    g_ego_bf[t * 2]     = packbf(v.x, v.y);
    g_ego_bf[t * 2 + 1] = packbf(v.z, v.w);
    if (real) {
        int i = t >> 4, c = t & 15;
        ((float4*)out)[i * 64 + c] = v;
    }
}

// ---------------------------------------------------------------------------
// spmm: side[row] += val * ego_bf16[col].
// EXACT round-12 execution shape (4 edges/thread, 16 threads/edge, one
// red.global.add.v4.f32 per edge per thread); only the gather narrows to
// uint2 (8B = 4 bf16) -> gather line traffic halved (1 line/edge/warp).
// ---------------------------------------------------------------------------
__device__ __forceinline__ void red4bf(float v, uint2 x, float* dst) {
    float f0 = __uint_as_float(x.x << 16);
    float f1 = __uint_as_float(x.x & 0xffff0000u);
    float f2 = __uint_as_float(x.y << 16);
    float f3 = __uint_as_float(x.y & 0xffff0000u);
    asm volatile("red.global.add.v4.f32 [%0], {%1,%2,%3,%4};"
                 :: "l"(dst), "f"(v * f0), "f"(v * f1),
                    "f"(v * f2), "f"(v * f3) : "memory");
}

__global__ void __launch_bounds__(256) spmm_kernel(
        const int*   __restrict__ rows,
        const int*   __restrict__ cols,
        const float* __restrict__ vals) {
    int t = blockIdx.x * 256 + threadIdx.x;
    int g = t >> 4;        // edge group of 4
    int c = t & 15;        // 4-elem chunk within the 64-float row
    int4   r4 = __ldg((const int4*)  rows + g);
    int4   c4 = __ldg((const int4*)  cols + g);
    float4 v4 = __ldg((const float4*)vals + g);
    const uint2* egob = (const uint2*)g_ego_bf;     // 16 uint2 per row
    uint2 x0 = __ldg(egob + (c4.x * 16 + c));
    uint2 x1 = __ldg(egob + (c4.y * 16 + c));
    uint2 x2 = __ldg(egob + (c4.z * 16 + c));
    uint2 x3 = __ldg(egob + (c4.w * 16 + c));

    red4bf(v4.x, x0, g_side + r4.x * 64 + c * 4);
    red4bf(v4.y, x1, g_side + r4.y * 64 + c * 4);
    red4bf(v4.z, x2, g_side + r4.z * 64 + c * 4);
    red4bf(v4.w, x3, g_side + r4.w * 64 + c * 4);
}

// ---------------------------------------------------------------------------
// Issue cp.async loads for one tile's raw ego/side (128 nodes x 64 f32 each).
// ---------------------------------------------------------------------------
__device__ __forceinline__ void issue_tile(char* sm, int buf, int tile, int tid) {
    uint32_t dE = smem_u32(sm + (buf ? OFF_E1 : OFF_E0));
    uint32_t dS = smem_u32(sm + (buf ? OFF_S1 : OFF_S0));
    const float* srcE = g_ego  + tile * (TILE_NODES * 64);
    const float* srcS = g_side + tile * (TILE_NODES * 64);
    #pragma unroll
    for (int it = 0; it < 8; it++) {
        int id   = it * 256 + tid;       // 0..2047
        int node = id >> 4;
        int c4   = id & 15;
        uint32_t dof = node * 256 + ((c4 ^ (node & 15)) << 4);
        int sof = node * 64 + c4 * 4;
        cp16(dE + dof, srcE + sof);
        cp16(dS + dof, srcS + sof);
    }
}

// ---------------------------------------------------------------------------
// Persistent dual-GEMM update (round-12 WIN structure, unchanged math).
// Epilogue also writes the bf16 mirror of next-layer ego for spmm.
// ---------------------------------------------------------------------------
__global__ void __launch_bounds__(256) update_kernel(
        const float* __restrict__ W1, const float* __restrict__ b1,
        const float* __restrict__ W2, const float* __restrict__ b2,
        float* __restrict__ out, int col4, int last) {
    extern __shared__ char sm[];
    int tid = threadIdx.x;
    int tx  = tid & 7;                // dim octet: dims tx*8 .. +7
    int ny  = tid >> 3;               // node quad: nodes ny*4 .. +3

    float b1v[8], b2v[8];
    #pragma unroll
    for (int d = 0; d < 8; d++) {
        b1v[d] = __ldg(b1 + tx * 8 + d);
        b2v[d] = __ldg(b2 + tx * 8 + d);
    }

    // stage W1/W2 k-major once per block
    float* sW1 = (float*)(sm + OFF_W1);
    float* sW2 = (float*)(sm + OFF_W2);
    for (int idx = tid; idx < 1024; idx += 256) {
        int kc = idx >> 6, j = idx & 63;
        float4 w1 = __ldg((const float4*)W1 + j * 16 + kc);
        float4 w2 = __ldg((const float4*)W2 + j * 16 + kc);
        int k0 = 4 * kc;
        sW1[(k0+0)*64 + j] = w1.x; sW1[(k0+1)*64 + j] = w1.y;
        sW1[(k0+2)*64 + j] = w1.z; sW1[(k0+3)*64 + j] = w1.w;
        sW2[(k0+0)*64 + j] = w2.x; sW2[(k0+1)*64 + j] = w2.y;
        sW2[(k0+2)*64 + j] = w2.z; sW2[(k0+3)*64 + j] = w2.w;
    }

    issue_tile(sm, 0, blockIdx.x, tid);
    asm volatile("cp.async.commit_group;" ::: "memory");

    int lt = 0;
    for (int t = blockIdx.x; t < N_TILES; t += UPD_GRID, lt++) {
        int buf = lt & 1;
        __syncthreads();                       // buffer buf^1 free to refill
        int tn = t + UPD_GRID;
        if (tn < N_TILES) {
            issue_tile(sm, buf ^ 1, tn, tid);
            asm volatile("cp.async.commit_group;" ::: "memory");
            asm volatile("cp.async.wait_group 1;" ::: "memory");
        } else {
            asm volatile("cp.async.wait_group 0;" ::: "memory");
        }
        __syncthreads();                       // tile t raw data visible

        // transform raw -> A (k-major), P (k-major)
        const char* bE = sm + (buf ? OFF_E1 : OFF_E0);
        const char* bS = sm + (buf ? OFF_S1 : OFF_S0);
        float* A = (float*)(sm + OFF_A);
        float* P = (float*)(sm + OFF_P);
        #pragma unroll
        for (int it = 0; it < 8; it++) {
            int idx  = it * 256 + tid;        // 0..2047
            int c4   = idx >> 7;              // k chunk 0..15
            int node = idx & 127;
            uint32_t ro = node * 256 + ((c4 ^ (node & 15)) << 4);
            float4 e = *(const float4*)(bE + ro);
            float4 s = *(const float4*)(bS + ro);
            int k0 = 4 * c4;
            A[(k0+0)*128 + node] = e.x + s.x;  P[(k0+0)*128 + node] = e.x * s.x;
            A[(k0+1)*128 + node] = e.y + s.y;  P[(k0+1)*128 + node] = e.y * s.y;
            A[(k0+2)*128 + node] = e.z + s.z;  P[(k0+2)*128 + node] = e.z * s.z;
            A[(k0+3)*128 + node] = e.w + s.w;  P[(k0+3)*128 + node] = e.w * s.w;
        }
        __syncthreads();

        // mainloop: 6 LDS.128 + 64 FMA per k
        float acc1[32], acc2[32];
        #pragma unroll
        for (int i = 0; i < 32; i++) { acc1[i] = 0.f; acc2[i] = 0.f; }

        const float4* A4  = (const float4*)(sm + OFF_A);
        const float4* P4  = (const float4*)(sm + OFF_P);
        const float4* W14 = (const float4*)(sm + OFF_W1);
        const float4* W24 = (const float4*)(sm + OFF_W2);

        #pragma unroll 4
        for (int k = 0; k < 64; k++) {
            float4 a   = A4 [k * 32 + ny];
            float4 p   = P4 [k * 32 + ny];
            float4 w1a = W14[k * 16 + tx * 2];
            float4 w1b = W14[k * 16 + tx * 2 + 1];
            float4 w2a = W24[k * 16 + tx * 2];
            float4 w2b = W24[k * 16 + tx * 2 + 1];
            float av[4] = {a.x, a.y, a.z, a.w};
            float pv[4] = {p.x, p.y, p.z, p.w};
            float w1[8] = {w1a.x, w1a.y, w1a.z, w1a.w, w1b.x, w1b.y, w1b.z, w1b.w};
            float w2[8] = {w2a.x, w2a.y, w2a.z, w2a.w, w2b.x, w2b.y, w2b.z, w2b.w};
            #pragma unroll
            for (int n = 0; n < 4; n++)
                #pragma unroll
                for (int d = 0; d < 8; d++) {
                    acc1[n * 8 + d] = fmaf(av[n], w1[d], acc1[n * 8 + d]);
                    acc2[n * 8 + d] = fmaf(pv[n], w2[d], acc2[n * 8 + d]);
                }
        }

        // epilogue
        #pragma unroll
        for (int n = 0; n < 4; n++) {
            float v[8], ss = 0.f;
            #pragma unroll
            for (int d = 0; d < 8; d++) {
                float y1 = acc1[n * 8 + d] + b1v[d];
                float y2 = acc2[n * 8 + d] + b2v[d];
                y1 = (y1 >= 0.f) ? y1 : NEG_SLOPE * y1;
                y2 = (y2 >= 0.f) ? y2 : NEG_SLOPE * y2;
                v[d] = y1 + y2;
                ss += v[d] * v[d];
            }
            ss += __shfl_xor_sync(0xffffffffu, ss, 1);
            ss += __shfl_xor_sync(0xffffffffu, ss, 2);
            ss += __shfl_xor_sync(0xffffffffu, ss, 4);
            float inv = 1.0f / fmaxf(sqrtf(ss), 1e-12f);
            int i = t * TILE_NODES + ny * 4 + n;
            float4 lo = make_float4(v[0], v[1], v[2], v[3]);
            float4 hi = make_float4(v[4], v[5], v[6], v[7]);
            if (!last) {
                ((float4*)g_ego)[i * 16 + tx * 2]     = lo;
                ((float4*)g_ego)[i * 16 + tx * 2 + 1] = hi;
                uint4 bf = make_uint4(packbf(v[0], v[1]), packbf(v[2], v[3]),
                                      packbf(v[4], v[5]), packbf(v[6], v[7]));
                ((uint4*)g_ego_bf)[i * 8 + tx] = bf;
            }
            if (i < N_NODES) {
                ((float4*)out)[i * 64 + col4 + tx * 2] =
                    make_float4(lo.x*inv, lo.y*inv, lo.z*inv, lo.w*inv);
                ((float4*)out)[i * 64 + col4 + tx * 2 + 1] =
                    make_float4(hi.x*inv, hi.y*inv, hi.z*inv, hi.w*inv);
            }
        }

        // zero g_side tile for next layer's spmm
        if (!last) {
            float4 z = make_float4(0.f, 0.f, 0.f, 0.f);
            #pragma unroll
            for (int it = 0; it < 8; it++)
                ((float4*)g_side)[t * 2048 + it * 256 + tid] = z;
        }
    }
}

// ---------------------------------------------------------------------------
// Inputs: edge_rows(i32), edge_cols(i32), edge_vals(f32), ego(f32 N*64),
// W1(3*64*64), b1(3*64), W2(3*64*64), b2(3*64).
// Output: float32 [150000, 256] rows = [ego | norm1 | norm2 | norm3].
// ---------------------------------------------------------------------------
extern "C" void kernel_launch(void* const* d_in, const int* in_sizes, int n_in,
                              void* d_out, int out_size) {
    const int*   rows = (const int*)  d_in[0];
    const int*   cols = (const int*)  d_in[1];
    const float* vals = (const float*)d_in[2];
    const float* ego  = (const float*)d_in[3];
    const float* W1   = (const float*)d_in[4];
    const float* b1   = (const float*)d_in[5];
    const float* W2   = (const float*)d_in[6];
    const float* b2   = (const float*)d_in[7];
    float* out = (float*)d_out;

    cudaFuncSetAttribute(update_kernel,
                         cudaFuncAttributeMaxDynamicSharedMemorySize,
                         UPD_SMEM_BYTES);

    dummy_kernel<<<1, 32>>>();                                    // launch 0
    init_kernel<<<(N_PAD * 16) / 256, 256>>>(ego, out);           // launch 1
    for (int k = 0; k < 3; k++) {
        spmm_kernel<<<(N_EDGES / 4 * 16) / 256, 256>>>(rows, cols, vals);
        update_kernel<<<UPD_GRID, 256, UPD_SMEM_BYTES>>>(
            W1 + k * 4096, b1 + k * 64,
            W2 + k * 4096, b2 + k * 64,
            out, (k + 1) * 16, k == 2);
    }
}